// round 13
// baseline (speedup 1.0000x reference)
#include <cuda_runtime.h>
#include <cuda_bf16.h>

#define BATCH 8192
#define TMAX  2048
#define ROWSTRIDE (TMAX + 1)   // 2049 ints per row (last element is T)
#define TILE 256               // 8 elements per lane; warp handles 2 rows

// Register-resident layered LUT, one entry per lane:
//   lane k holds entry k; entry 0 = identity; layer v (v=1..4) at base 2^v-1,
//   entry e = product of v consecutive per-obs matrices, v = floor(log2(e+1)),
//   obs bits = (e+1) - 2^v (chronologically first = LSB). Entries 0..30 used.
// float4 = (c00, c01, c10, c11); alpha' = C * alpha.

__device__ __forceinline__ float4 lut_get(const float4 mine, int e) {
    float4 r;
    r.x = __shfl_sync(0xFFFFFFFFu, mine.x, e);
    r.y = __shfl_sync(0xFFFFFFFFu, mine.y, e);
    r.z = __shfl_sync(0xFFFFFFFFu, mine.z, e);
    r.w = __shfl_sync(0xFFFFFFFFu, mine.w, e);
    return r;
}

// Ordered reduce (lane 0 earliest) into lane 0, fold into r, broadcast sum.
__device__ __forceinline__ float reduce_fold(float c00, float c01, float c10, float c11,
                                             float& r00, float& r01, float& r10, float& r11,
                                             int lane) {
    #pragma unroll
    for (int d = 1; d < 32; d <<= 1) {
        const float u00 = __shfl_down_sync(0xFFFFFFFFu, c00, d);
        const float u01 = __shfl_down_sync(0xFFFFFFFFu, c01, d);
        const float u10 = __shfl_down_sync(0xFFFFFFFFu, c10, d);
        const float u11 = __shfl_down_sync(0xFFFFFFFFu, c11, d);
        if (lane + d < 32) {                    // u is LATER in time: c = u * c
            const float q00 = u00 * c00 + u01 * c10;
            const float q01 = u00 * c01 + u01 * c11;
            const float q10 = u10 * c00 + u11 * c10;
            const float q11 = u10 * c01 + u11 * c11;
            c00 = q00; c01 = q01; c10 = q10; c11 = q11;
        }
    }
    if (lane == 0) {
        const float q00 = c00 * r00 + c01 * r10;
        const float q01 = c00 * r01 + c01 * r11;
        const float q10 = c10 * r00 + c11 * r10;
        const float q11 = c10 * r01 + c11 * r11;
        r00 = q00; r01 = q01; r10 = q10; r11 = q11;
    }
    // nonneg entries: sum == 0 <=> product exactly zero (and stays zero)
    const float s = r00 + r01 + r10 + r11;
    return __shfl_sync(0xFFFFFFFFu, s, 0);
}

__device__ __forceinline__ void process_row(const int* __restrict__ row,
                                            int T, int x0, int t0, int pos0,
                                            int pk1, int pk2, int pk3,
                                            int4 fa, int4 fb,
                                            const float4 mine, int lane,
                                            float E00, float E01, float E10, float E11,
                                            float p0f, float p1f,
                                            float* __restrict__ outp) {
    // peel elements [1, min(t0,T)) with a single layered lookup
    const int pe = t0 < T ? t0 : T;            // peel length = pe-1, in [0,3]
    const int pidx  = pk1 + 2 * pk2 + 4 * pk3;
    const int pmask = (1 << (pe - 1)) - 1;
    const float4 P = lut_get(mine, pmask + (pidx & pmask));
    float r00 = P.x, r01 = P.y, r10 = P.z, r11 = P.w;

    if (t0 < T) {
        // first tile (data already in registers)
        const int idxA = fa.x + 2 * fa.y + 4 * fa.z + 8 * fa.w;
        const int idxB = fb.x + 2 * fb.y + 4 * fb.z + 8 * fb.w;
        int rem = T - pos0;
        rem = rem < 0 ? 0 : (rem > 8 ? 8 : rem);
        const int vA = rem < 4 ? rem : 4;
        const int vB = rem - vA;
        const int mA = (1 << vA) - 1, mB = (1 << vB) - 1;
        const float4 MA = lut_get(mine, mA + (idxA & mA));
        const float4 MB = lut_get(mine, mB + (idxB & mB));

        const float c00 = MB.x * MA.x + MB.y * MA.z;
        const float c01 = MB.x * MA.y + MB.y * MA.w;
        const float c10 = MB.z * MA.x + MB.w * MA.z;
        const float c11 = MB.z * MA.y + MB.w * MA.w;
        float sum = reduce_fold(c00, c01, c10, c11, r00, r01, r10, r11, lane);

        // later tiles: essentially never run (underflow break)
        #pragma unroll 1
        for (int s = t0 + TILE; s < T && sum != 0.0f; s += TILE) {
            const int pos = s + (lane << 3);
            int4 a = make_int4(0, 0, 0, 0), b = a;
            if (pos < T) {
                if (pos + 8 <= ROWSTRIDE) {
                    const int4* p = (const int4*)(row + pos);
                    a = p[0]; b = p[1];
                } else {                       // tail at the very row end
                    const int v = T - pos;     // <= 6 here
                    a.x = row[pos];
                    if (v > 1) a.y = row[pos + 1];
                    if (v > 2) a.z = row[pos + 2];
                    if (v > 3) a.w = row[pos + 3];
                    if (v > 4) b.x = row[pos + 4];
                    if (v > 5) b.y = row[pos + 5];
                }
            }
            const int iA = a.x + 2 * a.y + 4 * a.z + 8 * a.w;
            const int iB = b.x + 2 * b.y + 4 * b.z + 8 * b.w;
            int rem2 = T - pos;
            rem2 = rem2 < 0 ? 0 : (rem2 > 8 ? 8 : rem2);
            const int vA2 = rem2 < 4 ? rem2 : 4;
            const int vB2 = rem2 - vA2;
            const int mA2 = (1 << vA2) - 1, mB2 = (1 << vB2) - 1;
            const float4 MA2 = lut_get(mine, mA2 + (iA & mA2));
            const float4 MB2 = lut_get(mine, mB2 + (iB & mB2));
            const float d00 = MB2.x * MA2.x + MB2.y * MA2.z;
            const float d01 = MB2.x * MA2.y + MB2.y * MA2.w;
            const float d10 = MB2.z * MA2.x + MB2.w * MA2.z;
            const float d11 = MB2.z * MA2.y + MB2.w * MA2.w;
            sum = reduce_fold(d00, d01, d10, d11, r00, r01, r10, r11, lane);
        }
    }

    if (lane == 0) {
        const float al0 = (x0 ? E01 : E00) * p0f;
        const float al1 = (x0 ? E11 : E10) * p1f;
        *outp = (r00 * al0 + r01 * al1) + (r10 * al0 + r11 * al1);
    }
}

__global__ __launch_bounds__(256)
void hmm_fwd_kernel(const int* __restrict__ xin,
                    const float* __restrict__ prior_l,
                    const float* __restrict__ trans_l,
                    const float* __restrict__ emis_l,
                    float* __restrict__ out) {
    const int tid  = threadIdx.x;
    const int wid  = tid >> 5;
    const int lane = tid & 31;
    const int row0 = (blockIdx.x * 8 + wid) * 2;   // warp owns rows row0, row0+1

    const int* __restrict__ rp0 = xin + (size_t)row0 * ROWSTRIDE;
    const int* __restrict__ rp1 = rp0 + ROWSTRIDE;

    // ---- issue ALL loads for both rows first (max MLP under const build) ----
    const int T0  = rp0[TMAX];
    const int x00 = rp0[0];
    const int mis0 = (row0 + 1) & 3;
    const int t00i = 1 + ((4 - mis0) & 3);         // in [1,4]
    const int apk1 = (t00i > 1) ? rp0[1] : 0;
    const int apk2 = (t00i > 2) ? rp0[2] : 0;
    const int apk3 = (t00i > 3) ? rp0[3] : 0;
    const int apos0 = t00i + (lane << 3);
    const int4* ap = (const int4*)(rp0 + apos0);
    const int4 afa = ap[0];
    const int4 afb = ap[1];

    const int T1  = rp1[TMAX];
    const int x01 = rp1[0];
    const int mis1 = (row0 + 2) & 3;
    const int t01i = 1 + ((4 - mis1) & 3);
    const int bpk1 = (t01i > 1) ? rp1[1] : 0;
    const int bpk2 = (t01i > 2) ? rp1[2] : 0;
    const int bpk3 = (t01i > 3) ? rp1[3] : 0;
    const int bpos0 = t01i + (lane << 3);
    const int4* bp = (const int4*)(rp1 + bpos0);
    const int4 bfa = bp[0];
    const int4 bfb = bp[1];

    // ---- softmax constants via sigmoid form (2-class softmax) ----
    const float p0f = __fdividef(1.0f, 1.0f + __expf(prior_l[1] - prior_l[0]));
    const float p1f = 1.0f - p0f;

    const float A00 = __fdividef(1.0f, 1.0f + __expf(trans_l[1] - trans_l[0]));
    const float A01 = 1.0f - A00;
    const float A10 = __fdividef(1.0f, 1.0f + __expf(trans_l[3] - trans_l[2]));
    const float A11 = 1.0f - A10;

    const float E00 = __fdividef(1.0f, 1.0f + __expf(emis_l[1] - emis_l[0]));
    const float E01 = 1.0f - E00;
    const float E10 = __fdividef(1.0f, 1.0f + __expf(emis_l[3] - emis_l[2]));
    const float E11 = 1.0f - E10;

    const float Ma00 = E00 * A00, Ma01 = E00 * A10, Ma10 = E10 * A01, Ma11 = E10 * A11;
    const float Mb00 = E01 * A00, Mb01 = E01 * A10, Mb10 = E11 * A01, Mb11 = E11 * A11;

    // ---- each lane builds LUT entry 'lane' in registers ----
    float4 mine = make_float4(1.f, 0.f, 0.f, 1.f);   // lane 0 identity; 31 unused
    if (lane >= 1 && lane <= 30) {
        const int n = lane + 1;
        const int v = 31 - __clz(n);           // layer
        const int idx = n - (1 << v);          // obs bits
        float c00 = 1.f, c01 = 0.f, c10 = 0.f, c11 = 1.f;
        for (int i = 0; i < v; ++i) {
            const int b = (idx >> i) & 1;
            const float m00 = b ? Mb00 : Ma00, m01 = b ? Mb01 : Ma01;
            const float m10 = b ? Mb10 : Ma10, m11 = b ? Mb11 : Ma11;
            const float q00 = m00 * c00 + m01 * c10;
            const float q01 = m00 * c01 + m01 * c11;
            const float q10 = m10 * c00 + m11 * c10;
            const float q11 = m10 * c01 + m11 * c11;
            c00 = q00; c01 = q01; c10 = q10; c11 = q11;
        }
        mine = make_float4(c00, c01, c10, c11);
    }

    process_row(rp0, T0, x00, t00i, apos0, apk1, apk2, apk3, afa, afb,
                mine, lane, E00, E01, E10, E11, p0f, p1f, out + row0);
    process_row(rp1, T1, x01, t01i, bpos0, bpk1, bpk2, bpk3, bfa, bfb,
                mine, lane, E00, E01, E10, E11, p0f, p1f, out + row0 + 1);
}

extern "C" void kernel_launch(void* const* d_in, const int* in_sizes, int n_in,
                              void* d_out, int out_size) {
    const int*   xin     = (const int*)d_in[0];
    const float* prior_l = (const float*)d_in[1];
    const float* trans_l = (const float*)d_in[2];
    const float* emis_l  = (const float*)d_in[3];
    float* out = (float*)d_out;

    const int blocks = BATCH / 16;     // 512 blocks, 8 warps, 2 rows per warp
    hmm_fwd_kernel<<<blocks, 256>>>(xin, prior_l, trans_l, emis_l, out);
}

// round 14
// speedup vs baseline: 1.0108x; 1.0108x over previous
#include <cuda_runtime.h>
#include <cuda_bf16.h>

#define BATCH 8192
#define TMAX  2048
#define ROWSTRIDE (TMAX + 1)   // 2049 ints per row (last element is T)
#define TILE 256               // 8 elements per lane, warp-per-row

// Register-resident layered LUT, one entry per lane:
//   lane k holds entry k; entry 0 = identity; layer v (v=1..4) at base 2^v-1,
//   entry e = product of v consecutive per-obs matrices, v = floor(log2(e+1)),
//   obs bits = (e+1) - 2^v (chronologically first = LSB). Entries 0..30 used.
// float4 = (c00, c01, c10, c11); alpha' = C * alpha.

__device__ __forceinline__ float4 lut_get(const float4 mine, int e) {
    float4 r;
    r.x = __shfl_sync(0xFFFFFFFFu, mine.x, e);
    r.y = __shfl_sync(0xFFFFFFFFu, mine.y, e);
    r.z = __shfl_sync(0xFFFFFFFFu, mine.z, e);
    r.w = __shfl_sync(0xFFFFFFFFu, mine.w, e);
    return r;
}

// Ordered reduce (lane 0 earliest) into lane 0, fold into r, broadcast sum.
__device__ __forceinline__ float reduce_fold(float c00, float c01, float c10, float c11,
                                             float& r00, float& r01, float& r10, float& r11,
                                             int lane) {
    #pragma unroll
    for (int d = 1; d < 32; d <<= 1) {
        const float u00 = __shfl_down_sync(0xFFFFFFFFu, c00, d);
        const float u01 = __shfl_down_sync(0xFFFFFFFFu, c01, d);
        const float u10 = __shfl_down_sync(0xFFFFFFFFu, c10, d);
        const float u11 = __shfl_down_sync(0xFFFFFFFFu, c11, d);
        if (lane + d < 32) {                    // u is LATER in time: c = u * c
            const float q00 = u00 * c00 + u01 * c10;
            const float q01 = u00 * c01 + u01 * c11;
            const float q10 = u10 * c00 + u11 * c10;
            const float q11 = u10 * c01 + u11 * c11;
            c00 = q00; c01 = q01; c10 = q10; c11 = q11;
        }
    }
    if (lane == 0) {
        const float q00 = c00 * r00 + c01 * r10;
        const float q01 = c00 * r01 + c01 * r11;
        const float q10 = c10 * r00 + c11 * r10;
        const float q11 = c10 * r01 + c11 * r11;
        r00 = q00; r01 = q01; r10 = q10; r11 = q11;
    }
    // nonneg entries: sum == 0 <=> product exactly zero (and stays zero)
    const float s = r00 + r01 + r10 + r11;
    return __shfl_sync(0xFFFFFFFFu, s, 0);
}

__global__ __launch_bounds__(128, 10)
void hmm_fwd_kernel(const int* __restrict__ xin,
                    const float* __restrict__ prior_l,
                    const float* __restrict__ trans_l,
                    const float* __restrict__ emis_l,
                    float* __restrict__ out) {
    const int tid  = threadIdx.x;
    const int wid  = tid >> 5;
    const int lane = tid & 31;
    const int row_id = blockIdx.x * 4 + wid;   // warp-per-row, fully independent

    const int* __restrict__ row = xin + (size_t)row_id * ROWSTRIDE;

    // ---- issue all loads first; their latency hides the constant build ----
    const int T  = row[TMAX];
    const int x0 = row[0];
    const int mis = (row_id + 1) & 3;          // row base ≡ (row_id+1) mod 4 ints
    const int t0  = 1 + ((4 - mis) & 3);       // 16B-aligned start, in [1,4]
    const int pk1 = (t0 > 1) ? row[1] : 0;
    const int pk2 = (t0 > 2) ? row[2] : 0;
    const int pk3 = (t0 > 3) ? row[3] : 0;

    const int pos0 = t0 + (lane << 3);         // <= 252: always in-bounds
    const int4* p0 = (const int4*)(row + pos0);
    const int4 fa = p0[0];
    const int4 fb = p0[1];

    // ---- softmax constants via sigmoid form (2-class softmax) ----
    const float p0f = __fdividef(1.0f, 1.0f + __expf(prior_l[1] - prior_l[0]));
    const float p1f = 1.0f - p0f;

    const float A00 = __fdividef(1.0f, 1.0f + __expf(trans_l[1] - trans_l[0]));
    const float A01 = 1.0f - A00;
    const float A10 = __fdividef(1.0f, 1.0f + __expf(trans_l[3] - trans_l[2]));
    const float A11 = 1.0f - A10;

    const float E00 = __fdividef(1.0f, 1.0f + __expf(emis_l[1] - emis_l[0]));
    const float E01 = 1.0f - E00;
    const float E10 = __fdividef(1.0f, 1.0f + __expf(emis_l[3] - emis_l[2]));
    const float E11 = 1.0f - E10;

    const float Ma00 = E00 * A00, Ma01 = E00 * A10, Ma10 = E10 * A01, Ma11 = E10 * A11;
    const float Mb00 = E01 * A00, Mb01 = E01 * A10, Mb10 = E11 * A01, Mb11 = E11 * A11;

    // ---- each lane builds LUT entry 'lane' in registers ----
    // entry e: n = e+1, layer v = floor(log2(n)), obs bits idx = n - 2^v
    float4 mine = make_float4(1.f, 0.f, 0.f, 1.f);   // lane 0 identity; 31 unused
    if (lane >= 1 && lane <= 30) {
        const int n = lane + 1;
        const int v = 31 - __clz(n);           // layer
        const int idx = n - (1 << v);          // obs bits
        float c00 = 1.f, c01 = 0.f, c10 = 0.f, c11 = 1.f;
        for (int i = 0; i < v; ++i) {
            const int b = (idx >> i) & 1;
            const float m00 = b ? Mb00 : Ma00, m01 = b ? Mb01 : Ma01;
            const float m10 = b ? Mb10 : Ma10, m11 = b ? Mb11 : Ma11;
            const float q00 = m00 * c00 + m01 * c10;
            const float q01 = m00 * c01 + m01 * c11;
            const float q10 = m10 * c00 + m11 * c10;
            const float q11 = m10 * c01 + m11 * c11;
            c00 = q00; c01 = q01; c10 = q10; c11 = q11;
        }
        mine = make_float4(c00, c01, c10, c11);
    }

    // ---- peel elements [1, min(t0,T)) with a single layered lookup ----
    const int pe = t0 < T ? t0 : T;            // peel length = pe-1, in [0,3]
    const int pidx  = pk1 + 2 * pk2 + 4 * pk3;
    const int pmask = (1 << (pe - 1)) - 1;
    const float4 P = lut_get(mine, pmask + (pidx & pmask));
    float r00 = P.x, r01 = P.y, r10 = P.z, r11 = P.w;

    if (t0 < T) {
        // ---- first tile (data already in flight) ----
        const int idxA = fa.x + 2 * fa.y + 4 * fa.z + 8 * fa.w;
        const int idxB = fb.x + 2 * fb.y + 4 * fb.z + 8 * fb.w;
        int rem = T - pos0;
        rem = rem < 0 ? 0 : (rem > 8 ? 8 : rem);
        const int vA = rem < 4 ? rem : 4;
        const int vB = rem - vA;
        const int mA = (1 << vA) - 1, mB = (1 << vB) - 1;
        const float4 MA = lut_get(mine, mA + (idxA & mA));
        const float4 MB = lut_get(mine, mB + (idxB & mB));

        const float c00 = MB.x * MA.x + MB.y * MA.z;
        const float c01 = MB.x * MA.y + MB.y * MA.w;
        const float c10 = MB.z * MA.x + MB.w * MA.z;
        const float c11 = MB.z * MA.y + MB.w * MA.w;
        float sum = reduce_fold(c00, c01, c10, c11, r00, r01, r10, r11, lane);

        // ---- later tiles: essentially never run (underflow break) ----
        #pragma unroll 1
        for (int s = t0 + TILE; s < T && sum != 0.0f; s += TILE) {
            const int pos = s + (lane << 3);
            int4 a = make_int4(0, 0, 0, 0), b = a;
            if (pos < T) {
                if (pos + 8 <= ROWSTRIDE) {
                    const int4* p = (const int4*)(row + pos);
                    a = p[0]; b = p[1];
                } else {                       // tail at the very row end
                    const int v = T - pos;     // <= 6 here
                    a.x = row[pos];
                    if (v > 1) a.y = row[pos + 1];
                    if (v > 2) a.z = row[pos + 2];
                    if (v > 3) a.w = row[pos + 3];
                    if (v > 4) b.x = row[pos + 4];
                    if (v > 5) b.y = row[pos + 5];
                }
            }
            const int iA = a.x + 2 * a.y + 4 * a.z + 8 * a.w;
            const int iB = b.x + 2 * b.y + 4 * b.z + 8 * b.w;
            int rem2 = T - pos;
            rem2 = rem2 < 0 ? 0 : (rem2 > 8 ? 8 : rem2);
            const int vA2 = rem2 < 4 ? rem2 : 4;
            const int vB2 = rem2 - vA2;
            const int mA2 = (1 << vA2) - 1, mB2 = (1 << vB2) - 1;
            const float4 MA2 = lut_get(mine, mA2 + (iA & mA2));
            const float4 MB2 = lut_get(mine, mB2 + (iB & mB2));
            const float d00 = MB2.x * MA2.x + MB2.y * MA2.z;
            const float d01 = MB2.x * MA2.y + MB2.y * MA2.w;
            const float d10 = MB2.z * MA2.x + MB2.w * MA2.z;
            const float d11 = MB2.z * MA2.y + MB2.w * MA2.w;
            sum = reduce_fold(d00, d01, d10, d11, r00, r01, r10, r11, lane);
        }
    }

    if (lane == 0) {
        const float al0 = (x0 ? E01 : E00) * p0f;
        const float al1 = (x0 ? E11 : E10) * p1f;
        // out = 1^T * P * alpha0 = (col0 sum)*al0 + (col1 sum)*al1
        out[row_id] = (r00 + r10) * al0 + (r01 + r11) * al1;
    }
}

extern "C" void kernel_launch(void* const* d_in, const int* in_sizes, int n_in,
                              void* d_out, int out_size) {
    const int*   xin     = (const int*)d_in[0];
    const float* prior_l = (const float*)d_in[1];
    const float* trans_l = (const float*)d_in[2];
    const float* emis_l  = (const float*)d_in[3];
    float* out = (float*)d_out;

    const int blocks = BATCH / 4;      // 2048 blocks, 4 independent warps each
    hmm_fwd_kernel<<<blocks, 128>>>(xin, prior_l, trans_l, emis_l, out);
}